// round 15
// baseline (speedup 1.0000x reference)
#include <cuda_runtime.h>
#include <math.h>

#define N_NODE        1000000
#define N_BOND        100000
#define KTW           40
#define MAX_ORDER     8
#define N_DOMAIN      10000
#define N_GROUP       12500        // N_BOND / MAX_ORDER
#define N_TW          500000       // N_GROUP * KTW (only these nodes twisted)
#define SIGMA_MAXF    3.14159265358979323846f

#define NTHR          128
// dilated k_fused: 8 active lanes per warp (every 4th lane), 8 groups/warp
#define GRP_PER_WARP  8
#define FUS_WARPS     ((N_GROUP + GRP_PER_WARP - 1) / GRP_PER_WARP)   // 1563
#define FUS_BLKS      ((FUS_WARPS + 3) / 4)                           // 391

// Per-level per-group affine transforms (9 R + 3 t), levels 0..7
__device__ __align__(16) float g_Mv[MAX_ORDER][N_GROUP * 12];
// version flag per group (zero-init; reset by k_reduce each replay)
__device__ int g_flag[N_GROUP];
// per-domain RT-ready flag (zero-init; reset by k_reduce each replay)
__device__ int g_rtflag[N_DOMAIN];
// per-domain reduction scratch: H(9)+sp(3)+sq(3)+pad
__device__ __align__(16) float g_red[N_DOMAIN * 16];
// per-domain rigid transform R(9)+t(3)
__device__ __align__(16) float g_RT[N_DOMAIN * 12];

__device__ __forceinline__ int ld_acq(const int* p) {
    int v;
    asm volatile("ld.acquire.gpu.global.b32 %0, [%1];" : "=r"(v) : "l"(p));
    return v;
}
__device__ __forceinline__ void st_rel(int* p, int v) {
    asm volatile("st.release.gpu.global.b32 [%0], %1;" :: "l"(p), "r"(v) : "memory");
}

__device__ __forceinline__ float3 xform(const float* __restrict__ buf, int h,
                                        float x, float y, float z) {
    const float4* m4 = (const float4*)&buf[h * 12];
    float4 m0 = m4[0], m1 = m4[1], m2 = m4[2];
    return make_float3(m0.x*x + m0.y*y + m0.z*z + m2.y,
                       m0.w*x + m1.x*y + m1.y*z + m2.z,
                       m1.z*x + m1.w*y + m2.x*z + m2.w);
}

// fp32 sin/cos: explicit range reduction to [-pi,pi], then MUFU trig.
__device__ __forceinline__ void my_sincosf(float ang, float* s, float* c) {
    const float INV2PI   = 0.15915494309189535f;
    const float TWOPI_HI = 6.28318548202514648f;
    const float TWOPI_LO = -1.7484556e-07f;
    float k = rintf(ang * INV2PI);
    float r = fmaf(-k, TWOPI_HI, ang);
    r = fmaf(-k, TWOPI_LO, r);
    *s = __sinf(r);
    *c = __cosf(r);
}

// ---------------------------------------------------------------------------
// Torsion: dataflow, LANE-DILUTED (8 active lanes per warp -> per-level warp
// wait is a max over ~16 producers instead of ~64, cutting convoy slack).
// __launch_bounds__(128,4) caps regs at 128 -> 4 blocks/SM -> 592 resident
// slots >= 391 blocks: the whole grid is co-resident (deadlock-free).
// ---------------------------------------------------------------------------
__global__ __launch_bounds__(NTHR, 4) void k_fused(const float* __restrict__ pos,
                                                   const int*   __restrict__ anno,
                                                   const float* __restrict__ info,
                                                   const float* __restrict__ eps,
                                                   const float* __restrict__ uni,
                                                   const int*   __restrict__ fprio) {
    int t = blockIdx.x * NTHR + threadIdx.x;
    int w = t >> 5;
    int l = t & 31;
    if (l & 3) return;                      // active lanes: 0,4,...,28
    int g = w * GRP_PER_WARP + (l >> 2);
    if (g >= N_GROUP) return;

    const int4* a4 = (const int4*)(anno + 24 * g);
    int4 A0 = a4[0], A1 = a4[1], A2 = a4[2], A3 = a4[3], A4 = a4[4], A5 = a4[5];
    int aw[24] = {A0.x,A0.y,A0.z,A0.w, A1.x,A1.y,A1.z,A1.w,
                  A2.x,A2.y,A2.z,A2.w, A3.x,A3.y,A3.z,A3.w,
                  A4.x,A4.y,A4.z,A4.w, A5.x,A5.y,A5.z,A5.w};
    int U[MAX_ORDER], Vn[MAX_ORDER];
    #pragma unroll
    for (int o = 0; o < MAX_ORDER; o++) {
        U[o]  = aw[3 * o + 1];
        Vn[o] = aw[3 * o + 2];
    }

    float pux[8], puy[8], puz[8], pvx[8], pvy[8], pvz[8];
    #pragma unroll
    for (int o = 0; o < MAX_ORDER; o++) {
        int nu = U[o], nv = Vn[o];
        pux[o] = pos[3*nu]; puy[o] = pos[3*nu+1]; puz[o] = pos[3*nu+2];
        pvx[o] = pos[3*nv]; pvy[o] = pos[3*nv+1]; pvz[o] = pos[3*nv+2];
    }

    const float4* i4 = (const float4*)(info + 8 * g);
    const float4* e4 = (const float4*)(eps + 8 * g);
    const float4* u4 = (const float4*)(uni + 8 * g);
    float4 I0 = i4[0], I1 = i4[1];
    float4 E0 = e4[0], E1 = e4[1];
    float4 X0 = u4[0], X1 = u4[1];
    float il[8] = {I0.x,I0.y,I0.z,I0.w, I1.x,I1.y,I1.z,I1.w};
    float ep[8] = {E0.x,E0.y,E0.z,E0.w, E1.x,E1.y,E1.z,E1.w};
    float un[8] = {X0.x,X0.y,X0.z,X0.w, X1.x,X1.y,X1.z,X1.w};
    int fp = fprio[0];
    float S[8], C[8];
    #pragma unroll
    for (int o = 0; o < MAX_ORDER; o++) {
        float ang = ep[o] * (1.0f - il[o]) * SIGMA_MAXF;
        if (fp != 0 && il[o] == 0.0f) ang = un[o];
        my_sincosf(ang, &S[o], &C[o]);
    }

    float M[12];

    #pragma unroll
    for (int o = 0; o < MAX_ORDER; o++) {
        float ux = pux[o], uy = puy[o], uz = puz[o];
        float vx = pvx[o], vy = pvy[o], vz = pvz[o];

        if (o > 0) {
            int nu = U[o];
            if (nu < N_TW) {
                int h = nu / KTW;
                if (h == g) {
                    float tx = M[0]*ux + M[1]*uy + M[2]*uz + M[9];
                    float ty = M[3]*ux + M[4]*uy + M[5]*uz + M[10];
                    float tz = M[6]*ux + M[7]*uy + M[8]*uz + M[11];
                    ux = tx; uy = ty; uz = tz;
                } else {
                    while (ld_acq(&g_flag[h]) < o) { }
                    float3 tt = xform(g_Mv[o-1], h, ux, uy, uz);
                    ux = tt.x; uy = tt.y; uz = tt.z;
                }
            }
            int nv = Vn[o];
            if (nv < N_TW) {
                int h = nv / KTW;
                if (h == g) {
                    float tx = M[0]*vx + M[1]*vy + M[2]*vz + M[9];
                    float ty = M[3]*vx + M[4]*vy + M[5]*vz + M[10];
                    float tz = M[6]*vx + M[7]*vy + M[8]*vz + M[11];
                    vx = tx; vy = ty; vz = tz;
                } else {
                    while (ld_acq(&g_flag[h]) < o) { }
                    float3 tt = xform(g_Mv[o-1], h, vx, vy, vz);
                    vx = tt.x; vy = tt.y; vz = tt.z;
                }
            }
        }

        float ax = vx - ux, ay = vy - uy, az = vz - uz;
        float nrm = sqrtf(ax*ax + ay*ay + az*az) + 1e-12f;
        float inv = 1.0f / nrm;
        ax *= inv; ay *= inv; az *= inv;

        float s = S[o], c = C[o], omc = 1.0f - c;
        float r0 = c + omc*ax*ax;
        float r1 = -s*az + omc*ax*ay;
        float r2 =  s*ay + omc*ax*az;
        float r3 =  s*az + omc*ay*ax;
        float r4 = c + omc*ay*ay;
        float r5 = -s*ax + omc*ay*az;
        float r6 = -s*ay + omc*az*ax;
        float r7 =  s*ax + omc*az*ay;
        float r8 = c + omc*az*az;
        float t0 = vx - (r0*vx + r1*vy + r2*vz);
        float t1 = vy - (r3*vx + r4*vy + r5*vz);
        float t2 = vz - (r6*vx + r7*vy + r8*vz);

        if (o == 0) {
            M[0]=r0; M[1]=r1; M[2]=r2; M[3]=r3; M[4]=r4; M[5]=r5;
            M[6]=r6; M[7]=r7; M[8]=r8; M[9]=t0; M[10]=t1; M[11]=t2;
        } else {
            float m0=M[0],m1=M[1],m2=M[2],m3=M[3],m4=M[4],m5=M[5];
            float m6=M[6],m7=M[7],m8=M[8],mt0=M[9],mt1=M[10],mt2=M[11];
            M[0] = r0*m0 + r1*m3 + r2*m6;
            M[1] = r0*m1 + r1*m4 + r2*m7;
            M[2] = r0*m2 + r1*m5 + r2*m8;
            M[3] = r3*m0 + r4*m3 + r5*m6;
            M[4] = r3*m1 + r4*m4 + r5*m7;
            M[5] = r3*m2 + r4*m5 + r5*m8;
            M[6] = r6*m0 + r7*m3 + r8*m6;
            M[7] = r6*m1 + r7*m4 + r8*m7;
            M[8] = r6*m2 + r7*m5 + r8*m8;
            M[9]  = r0*mt0 + r1*mt1 + r2*mt2 + t0;
            M[10] = r3*mt0 + r4*mt1 + r5*mt2 + t1;
            M[11] = r6*mt0 + r7*mt1 + r8*mt2 + t2;
        }

        float4* w4 = (float4*)&g_Mv[o][g * 12];
        w4[0] = make_float4(M[0], M[1], M[2], M[3]);
        w4[1] = make_float4(M[4], M[5], M[6], M[7]);
        w4[2] = make_float4(M[8], M[9], M[10], M[11]);
        st_rel(&g_flag[g], o + 1);
    }
}

// ---------------------------------------------------------------------------
// Reduce: warp per domain. Writes H(9)+sp(3)+sq(3). Resets both flag arrays.
// ---------------------------------------------------------------------------
__global__ __launch_bounds__(256) void k_reduce(const float* __restrict__ pos) {
    int t = blockIdx.x * blockDim.x + threadIdx.x;
    if (t < N_GROUP) g_flag[t] = 0;
    if (t < N_DOMAIN) g_rtflag[t] = 0;

    int wid  = t >> 5;
    int lane = t & 31;
    if (wid >= N_DOMAIN) return;
    int base = wid * 100;
    const float* __restrict__ M = g_Mv[MAX_ORDER - 1];

    float sp0=0,sp1=0,sp2=0,sq0=0,sq1=0,sq2=0;
    float h00=0,h01=0,h02=0,h10=0,h11=0,h12=0,h20=0,h21=0,h22=0;

    #pragma unroll
    for (int i = 0; i < 4; i++) {
        int idx = lane + 32 * i;
        if (idx < 100) {
            int n = base + idx;
            float qx = pos[3*n], qy = pos[3*n+1], qz = pos[3*n+2];
            float px, py, pz;
            if (n < N_TW) {
                float3 P = xform(M, n / KTW, qx, qy, qz);
                px = P.x; py = P.y; pz = P.z;
            } else { px = qx; py = qy; pz = qz; }
            sp0+=px; sp1+=py; sp2+=pz;
            sq0+=qx; sq1+=qy; sq2+=qz;
            h00+=px*qx; h01+=px*qy; h02+=px*qz;
            h10+=py*qx; h11+=py*qy; h12+=py*qz;
            h20+=pz*qx; h21+=pz*qy; h22+=pz*qz;
        }
    }

    #define WRED(v) { v += __shfl_xor_sync(0xffffffffu, v, 16); \
                      v += __shfl_xor_sync(0xffffffffu, v, 8);  \
                      v += __shfl_xor_sync(0xffffffffu, v, 4);  \
                      v += __shfl_xor_sync(0xffffffffu, v, 2);  \
                      v += __shfl_xor_sync(0xffffffffu, v, 1); }
    WRED(sp0) WRED(sp1) WRED(sp2) WRED(sq0) WRED(sq1) WRED(sq2)
    WRED(h00) WRED(h01) WRED(h02) WRED(h10) WRED(h11) WRED(h12)
    WRED(h20) WRED(h21) WRED(h22)
    #undef WRED

    if (lane == 0) {
        float4* r = (float4*)&g_red[wid * 16];
        r[0] = make_float4(h00, h01, h02, h10);
        r[1] = make_float4(h11, h12, h20, h21);
        r[2] = make_float4(h22, sp0, sp1, sp2);
        r[3] = make_float4(sq0, sq1, sq2, 0.0f);
    }
}

// ---------------------------------------------------------------------------
// Solve + apply, merged (R11-proven). Threads 0..N_DOMAIN-1 solve one domain
// each and release a flag; every thread then applies node n = global tid,
// polling its domain's flag AFTER issuing its own position/M loads.
// ---------------------------------------------------------------------------
__global__ __launch_bounds__(256, 5) void k_sapply(const float* __restrict__ pos,
                                                   float* __restrict__ out) {
    int t = blockIdx.x * blockDim.x + threadIdx.x;
    if (t >= N_NODE) return;

    // ---- solver role ----
    if (t < N_DOMAIN) {
        int d = t;
        const float4* r = (const float4*)&g_red[d * 16];
        float4 r0 = r[0], r1 = r[1], r2 = r[2], r3 = r[3];
        float h00=r0.x,h01=r0.y,h02=r0.z,h10=r0.w;
        float h11=r1.x,h12=r1.y,h20=r1.z,h21=r1.w;
        float h22=r2.x,sp0=r2.y,sp1=r2.z,sp2=r2.w;
        float sq0=r3.x,sq1=r3.y,sq2=r3.z;

        const float invc = 0.01f;
        float cpx=sp0*invc, cpy=sp1*invc, cpz=sp2*invc;
        float cqx=sq0*invc, cqy=sq1*invc, cqz=sq2*invc;
        float H00=h00-sp0*sq0*invc, H01=h01-sp0*sq1*invc, H02=h02-sp0*sq2*invc;
        float H10=h10-sp1*sq0*invc, H11=h11-sp1*sq1*invc, H12=h12-sp1*sq2*invc;
        float H20=h20-sp2*sq0*invc, H21=h21-sp2*sq1*invc, H22=h22-sp2*sq2*invc;

        float A[4][4];
        A[0][0] = H00 + H11 + H22;
        A[0][1] = H12 - H21;
        A[0][2] = H20 - H02;
        A[0][3] = H01 - H10;
        A[1][1] = H00 - H11 - H22;
        A[1][2] = H01 + H10;
        A[1][3] = H20 + H02;
        A[2][2] = -H00 + H11 - H22;
        A[2][3] = H12 + H21;
        A[3][3] = -H00 - H11 + H22;
        A[1][0]=A[0][1]; A[2][0]=A[0][2]; A[3][0]=A[0][3];
        A[2][1]=A[1][2]; A[3][1]=A[1][3]; A[3][2]=A[2][3];

        float V[4][4] = {{1,0,0,0},{0,1,0,0},{0,0,1,0},{0,0,0,1}};

        #pragma unroll
        for (int sweep = 0; sweep < 4; sweep++) {
            #pragma unroll
            for (int p = 0; p < 3; p++) {
                #pragma unroll
                for (int q = p + 1; q < 4; q++) {
                    float apq = A[p][q];
                    float theta = (A[q][q] - A[p][p]) * __fdividef(0.5f, apq);
                    float tt = __fdividef(1.0f, fabsf(theta) + __fsqrt_rn(fmaf(theta, theta, 1.0f)));
                    tt = (theta < 0.0f) ? -tt : tt;
                    bool ok = fabsf(apq) > 1e-30f;
                    float cc = ok ? rsqrtf(fmaf(tt, tt, 1.0f)) : 1.0f;
                    float ss = ok ? tt * cc : 0.0f;
                    #pragma unroll
                    for (int k = 0; k < 4; k++) {
                        float t1 = A[p][k], t2 = A[q][k];
                        A[p][k] = cc*t1 - ss*t2;
                        A[q][k] = ss*t1 + cc*t2;
                    }
                    #pragma unroll
                    for (int k = 0; k < 4; k++) {
                        float t1 = A[k][p], t2 = A[k][q];
                        A[k][p] = cc*t1 - ss*t2;
                        A[k][q] = ss*t1 + cc*t2;
                    }
                    #pragma unroll
                    for (int k = 0; k < 4; k++) {
                        float t1 = V[k][p], t2 = V[k][q];
                        V[k][p] = cc*t1 - ss*t2;
                        V[k][q] = ss*t1 + cc*t2;
                    }
                }
            }
        }

        int kbest = 0;
        float best = A[0][0];
        #pragma unroll
        for (int k = 1; k < 4; k++)
            if (A[k][k] > best) { best = A[k][k]; kbest = k; }
        float qw=V[0][kbest], qx=V[1][kbest], qy=V[2][kbest], qz=V[3][kbest];
        float qn = rsqrtf(qw*qw + qx*qx + qy*qy + qz*qz);
        qw*=qn; qx*=qn; qy*=qn; qz*=qn;

        float R00 = qw*qw + qx*qx - qy*qy - qz*qz;
        float R01 = 2.0f*(qx*qy - qw*qz);
        float R02 = 2.0f*(qx*qz + qw*qy);
        float R10 = 2.0f*(qx*qy + qw*qz);
        float R11 = qw*qw - qx*qx + qy*qy - qz*qz;
        float R12 = 2.0f*(qy*qz - qw*qx);
        float R20 = 2.0f*(qx*qz - qw*qy);
        float R21 = 2.0f*(qy*qz + qw*qx);
        float R22 = qw*qw - qx*qx - qy*qy + qz*qz;

        float tx = cqx - (R00*cpx + R01*cpy + R02*cpz);
        float ty = cqy - (R10*cpx + R11*cpy + R12*cpz);
        float tz = cqz - (R20*cpx + R21*cpy + R22*cpz);

        float4* w = (float4*)&g_RT[d * 12];
        w[0] = make_float4(R00, R01, R02, R10);
        w[1] = make_float4(R11, R12, R20, R21);
        w[2] = make_float4(R22, tx, ty, tz);
        st_rel(&g_rtflag[d], 1);
    }

    // ---- apply role: node n = t ----
    int n = t;
    float qx = pos[3*n], qy = pos[3*n+1], qz = pos[3*n+2];
    float px, py, pz;
    if (n < N_TW) {
        float3 P = xform(g_Mv[MAX_ORDER - 1], n / KTW, qx, qy, qz);
        px = P.x; py = P.y; pz = P.z;
    } else { px = qx; py = qy; pz = qz; }

    int d = n / 100;
    while (ld_acq(&g_rtflag[d]) == 0) { }

    const float4* r = (const float4*)&g_RT[d * 12];
    float4 R0 = r[0], R1 = r[1], R2 = r[2];
    out[3*n+0] = R0.x*px + R0.y*py + R0.z*pz + R2.y;
    out[3*n+1] = R0.w*px + R1.x*py + R1.y*pz + R2.z;
    out[3*n+2] = R1.z*px + R1.w*py + R2.x*pz + R2.w;
}

// ---------------------------------------------------------------------------
extern "C" void kernel_launch(void* const* d_in, const int* in_sizes, int n_in,
                              void* d_out, int out_size) {
    const float* pos   = (const float*)d_in[0];
    const float* info  = (const float*)d_in[1];
    const int*   anno  = (const int*)d_in[2];
    const float* eps   = (const float*)d_in[6];
    const float* uni   = (const float*)d_in[7];
    const int*   fprio = (const int*)d_in[8];
    float* out = (float*)d_out;

    k_fused<<<FUS_BLKS, NTHR>>>(pos, anno, info, eps, uni, fprio);
    k_reduce<<<(N_DOMAIN * 32 + 255) / 256, 256>>>(pos);
    k_sapply<<<(N_NODE + 255) / 256, 256>>>(pos, out);
}

// round 16
// speedup vs baseline: 2.0934x; 2.0934x over previous
#include <cuda_runtime.h>
#include <math.h>

#define N_NODE        1000000
#define N_BOND        100000
#define KTW           40
#define MAX_ORDER     8
#define N_DOMAIN      10000
#define N_GROUP       12500        // N_BOND / MAX_ORDER
#define N_TW          500000       // N_GROUP * KTW (only these nodes twisted)
#define SIGMA_MAXF    3.14159265358979323846f

#define NTHR          128
#define FUS_THREADS   (2 * N_GROUP)                       // 25000 (pair per group)
#define FUS_BLKS      ((FUS_THREADS + NTHR - 1) / NTHR)   // 196

// Per-level per-group affine transforms (9 R + 3 t), levels 0..7
__device__ __align__(16) float g_Mv[MAX_ORDER][N_GROUP * 12];
// version flag per group (zero-init; reset by k_reduce each replay)
__device__ int g_flag[N_GROUP];
// per-domain RT-ready flag (zero-init; reset by k_reduce each replay)
__device__ int g_rtflag[N_DOMAIN];
// per-domain reduction scratch: H(9)+sp(3)+sq(3)+pad
__device__ __align__(16) float g_red[N_DOMAIN * 16];
// per-domain rigid transform R(9)+t(3)
__device__ __align__(16) float g_RT[N_DOMAIN * 12];

__device__ __forceinline__ int ld_acq(const int* p) {
    int v;
    asm volatile("ld.acquire.gpu.global.b32 %0, [%1];" : "=r"(v) : "l"(p));
    return v;
}
__device__ __forceinline__ void st_rel(int* p, int v) {
    asm volatile("st.release.gpu.global.b32 [%0], %1;" :: "l"(p), "r"(v) : "memory");
}

__device__ __forceinline__ float3 xform(const float* __restrict__ buf, int h,
                                        float x, float y, float z) {
    const float4* m4 = (const float4*)&buf[h * 12];
    float4 m0 = m4[0], m1 = m4[1], m2 = m4[2];
    return make_float3(m0.x*x + m0.y*y + m0.z*z + m2.y,
                       m0.w*x + m1.x*y + m1.y*z + m2.z,
                       m1.z*x + m1.w*y + m2.x*z + m2.w);
}

// fp32 sin/cos: explicit range reduction to [-pi,pi], then MUFU trig.
__device__ __forceinline__ void my_sincosf(float ang, float* s, float* c) {
    const float INV2PI   = 0.15915494309189535f;
    const float TWOPI_HI = 6.28318548202514648f;
    const float TWOPI_LO = -1.7484556e-07f;
    float k = rintf(ang * INV2PI);
    float r = fmaf(-k, TWOPI_HI, ang);
    r = fmaf(-k, TWOPI_LO, r);
    *s = __sinf(r);
    *c = __cosf(r);
}

// ---------------------------------------------------------------------------
// Torsion: pair-split dataflow. TWO threads per group: even lane owns u,
// odd lane owns v. Each lane polls ONE flag (single-load loop, proven fast)
// and does ONE gather; endpoints exchanged by shfl_xor(1); both lanes
// redundantly compose M (bitwise identical); even lane publishes.
// Tail threads shadow the last group (no publish) so full-warp shuffles work.
// ---------------------------------------------------------------------------
__global__ __launch_bounds__(NTHR) void k_fused(const float* __restrict__ pos,
                                                const int*   __restrict__ anno,
                                                const float* __restrict__ info,
                                                const float* __restrict__ eps,
                                                const float* __restrict__ uni,
                                                const int*   __restrict__ fprio) {
    int t = blockIdx.x * NTHR + threadIdx.x;
    int g = t >> 1;
    int role = t & 1;                      // 0 = u endpoint, 1 = v endpoint
    bool valid = (g < N_GROUP);
    if (!valid) g = N_GROUP - 1;           // shadow work; never publish

    const int4* a4 = (const int4*)(anno + 24 * g);
    int4 A0 = a4[0], A1 = a4[1], A2 = a4[2], A3 = a4[3], A4 = a4[4], A5 = a4[5];
    int aw[24] = {A0.x,A0.y,A0.z,A0.w, A1.x,A1.y,A1.z,A1.w,
                  A2.x,A2.y,A2.z,A2.w, A3.x,A3.y,A3.z,A3.w,
                  A4.x,A4.y,A4.z,A4.w, A5.x,A5.y,A5.z,A5.w};
    int NN[MAX_ORDER];                     // this lane's endpoint node per level
    #pragma unroll
    for (int o = 0; o < MAX_ORDER; o++)
        NN[o] = aw[3 * o + 1 + role];

    // prefetch this lane's endpoint raw positions (independent LDGs)
    float pnx[8], pny[8], pnz[8];
    #pragma unroll
    for (int o = 0; o < MAX_ORDER; o++) {
        int n = NN[o];
        pnx[o] = pos[3*n]; pny[o] = pos[3*n+1]; pnz[o] = pos[3*n+2];
    }

    const float4* i4 = (const float4*)(info + 8 * g);
    const float4* e4 = (const float4*)(eps + 8 * g);
    const float4* u4 = (const float4*)(uni + 8 * g);
    float4 I0 = i4[0], I1 = i4[1];
    float4 E0 = e4[0], E1 = e4[1];
    float4 X0 = u4[0], X1 = u4[1];
    float il[8] = {I0.x,I0.y,I0.z,I0.w, I1.x,I1.y,I1.z,I1.w};
    float ep[8] = {E0.x,E0.y,E0.z,E0.w, E1.x,E1.y,E1.z,E1.w};
    float un[8] = {X0.x,X0.y,X0.z,X0.w, X1.x,X1.y,X1.z,X1.w};
    int fp = fprio[0];
    float S[8], C[8];
    #pragma unroll
    for (int o = 0; o < MAX_ORDER; o++) {
        float ang = ep[o] * (1.0f - il[o]) * SIGMA_MAXF;
        if (fp != 0 && il[o] == 0.0f) ang = un[o];
        my_sincosf(ang, &S[o], &C[o]);
    }

    float M[12];                           // redundant copy in both lanes

    #pragma unroll
    for (int o = 0; o < MAX_ORDER; o++) {
        float x = pnx[o], y = pny[o], z = pnz[o];

        if (o > 0) {
            int nn = NN[o];
            if (nn < N_TW) {
                int h = nn / KTW;
                if (h == g) {
                    float tx = M[0]*x + M[1]*y + M[2]*z + M[9];
                    float ty = M[3]*x + M[4]*y + M[5]*z + M[10];
                    float tz = M[6]*x + M[7]*y + M[8]*z + M[11];
                    x = tx; y = ty; z = tz;
                } else {
                    while (ld_acq(&g_flag[h]) < o) { }   // single-load poll
                    float3 tt = xform(g_Mv[o-1], h, x, y, z);
                    x = tt.x; y = tt.y; z = tt.z;
                }
            }
        }

        // pair exchange (u <-> v), whole warp participates
        float ox = __shfl_xor_sync(0xffffffffu, x, 1);
        float oy = __shfl_xor_sync(0xffffffffu, y, 1);
        float oz = __shfl_xor_sync(0xffffffffu, z, 1);
        float ux, uy, uz, vx, vy, vz;
        if (role == 0) { ux = x;  uy = y;  uz = z;  vx = ox; vy = oy; vz = oz; }
        else           { ux = ox; uy = oy; uz = oz; vx = x;  vy = y;  vz = z;  }

        float ax = vx - ux, ay = vy - uy, az = vz - uz;
        float nrm = sqrtf(ax*ax + ay*ay + az*az) + 1e-12f;
        float inv = 1.0f / nrm;
        ax *= inv; ay *= inv; az *= inv;

        float s = S[o], c = C[o], omc = 1.0f - c;
        float r0 = c + omc*ax*ax;
        float r1 = -s*az + omc*ax*ay;
        float r2 =  s*ay + omc*ax*az;
        float r3 =  s*az + omc*ay*ax;
        float r4 = c + omc*ay*ay;
        float r5 = -s*ax + omc*ay*az;
        float r6 = -s*ay + omc*az*ax;
        float r7 =  s*ax + omc*az*ay;
        float r8 = c + omc*az*az;
        float t0 = vx - (r0*vx + r1*vy + r2*vz);
        float t1 = vy - (r3*vx + r4*vy + r5*vz);
        float t2 = vz - (r6*vx + r7*vy + r8*vz);

        if (o == 0) {
            M[0]=r0; M[1]=r1; M[2]=r2; M[3]=r3; M[4]=r4; M[5]=r5;
            M[6]=r6; M[7]=r7; M[8]=r8; M[9]=t0; M[10]=t1; M[11]=t2;
        } else {
            float m0=M[0],m1=M[1],m2=M[2],m3=M[3],m4=M[4],m5=M[5];
            float m6=M[6],m7=M[7],m8=M[8],mt0=M[9],mt1=M[10],mt2=M[11];
            M[0] = r0*m0 + r1*m3 + r2*m6;
            M[1] = r0*m1 + r1*m4 + r2*m7;
            M[2] = r0*m2 + r1*m5 + r2*m8;
            M[3] = r3*m0 + r4*m3 + r5*m6;
            M[4] = r3*m1 + r4*m4 + r5*m7;
            M[5] = r3*m2 + r4*m5 + r5*m8;
            M[6] = r6*m0 + r7*m3 + r8*m6;
            M[7] = r6*m1 + r7*m4 + r8*m7;
            M[8] = r6*m2 + r7*m5 + r8*m8;
            M[9]  = r0*mt0 + r1*mt1 + r2*mt2 + t0;
            M[10] = r3*mt0 + r4*mt1 + r5*mt2 + t1;
            M[11] = r6*mt0 + r7*mt1 + r8*mt2 + t2;
        }

        if (valid && role == 0) {
            float4* w4 = (float4*)&g_Mv[o][g * 12];
            w4[0] = make_float4(M[0], M[1], M[2], M[3]);
            w4[1] = make_float4(M[4], M[5], M[6], M[7]);
            w4[2] = make_float4(M[8], M[9], M[10], M[11]);
            st_rel(&g_flag[g], o + 1);
        }
    }
}

// ---------------------------------------------------------------------------
// Reduce: warp per domain. Writes H(9)+sp(3)+sq(3). Resets both flag arrays.
// ---------------------------------------------------------------------------
__global__ __launch_bounds__(256) void k_reduce(const float* __restrict__ pos) {
    int t = blockIdx.x * blockDim.x + threadIdx.x;
    if (t < N_GROUP) g_flag[t] = 0;
    if (t < N_DOMAIN) g_rtflag[t] = 0;

    int wid  = t >> 5;
    int lane = t & 31;
    if (wid >= N_DOMAIN) return;
    int base = wid * 100;
    const float* __restrict__ M = g_Mv[MAX_ORDER - 1];

    float sp0=0,sp1=0,sp2=0,sq0=0,sq1=0,sq2=0;
    float h00=0,h01=0,h02=0,h10=0,h11=0,h12=0,h20=0,h21=0,h22=0;

    #pragma unroll
    for (int i = 0; i < 4; i++) {
        int idx = lane + 32 * i;
        if (idx < 100) {
            int n = base + idx;
            float qx = pos[3*n], qy = pos[3*n+1], qz = pos[3*n+2];
            float px, py, pz;
            if (n < N_TW) {
                float3 P = xform(M, n / KTW, qx, qy, qz);
                px = P.x; py = P.y; pz = P.z;
            } else { px = qx; py = qy; pz = qz; }
            sp0+=px; sp1+=py; sp2+=pz;
            sq0+=qx; sq1+=qy; sq2+=qz;
            h00+=px*qx; h01+=px*qy; h02+=px*qz;
            h10+=py*qx; h11+=py*qy; h12+=py*qz;
            h20+=pz*qx; h21+=pz*qy; h22+=pz*qz;
        }
    }

    #define WRED(v) { v += __shfl_xor_sync(0xffffffffu, v, 16); \
                      v += __shfl_xor_sync(0xffffffffu, v, 8);  \
                      v += __shfl_xor_sync(0xffffffffu, v, 4);  \
                      v += __shfl_xor_sync(0xffffffffu, v, 2);  \
                      v += __shfl_xor_sync(0xffffffffu, v, 1); }
    WRED(sp0) WRED(sp1) WRED(sp2) WRED(sq0) WRED(sq1) WRED(sq2)
    WRED(h00) WRED(h01) WRED(h02) WRED(h10) WRED(h11) WRED(h12)
    WRED(h20) WRED(h21) WRED(h22)
    #undef WRED

    if (lane == 0) {
        float4* r = (float4*)&g_red[wid * 16];
        r[0] = make_float4(h00, h01, h02, h10);
        r[1] = make_float4(h11, h12, h20, h21);
        r[2] = make_float4(h22, sp0, sp1, sp2);
        r[3] = make_float4(sq0, sq1, sq2, 0.0f);
    }
}

// ---------------------------------------------------------------------------
// Solve + apply, merged (R11-proven). Threads 0..N_DOMAIN-1 solve one domain
// each and release a flag; every thread then applies node n = global tid,
// polling its domain's flag AFTER issuing its own position/M loads.
// ---------------------------------------------------------------------------
__global__ __launch_bounds__(256, 5) void k_sapply(const float* __restrict__ pos,
                                                   float* __restrict__ out) {
    int t = blockIdx.x * blockDim.x + threadIdx.x;
    if (t >= N_NODE) return;

    // ---- solver role ----
    if (t < N_DOMAIN) {
        int d = t;
        const float4* r = (const float4*)&g_red[d * 16];
        float4 r0 = r[0], r1 = r[1], r2 = r[2], r3 = r[3];
        float h00=r0.x,h01=r0.y,h02=r0.z,h10=r0.w;
        float h11=r1.x,h12=r1.y,h20=r1.z,h21=r1.w;
        float h22=r2.x,sp0=r2.y,sp1=r2.z,sp2=r2.w;
        float sq0=r3.x,sq1=r3.y,sq2=r3.z;

        const float invc = 0.01f;
        float cpx=sp0*invc, cpy=sp1*invc, cpz=sp2*invc;
        float cqx=sq0*invc, cqy=sq1*invc, cqz=sq2*invc;
        float H00=h00-sp0*sq0*invc, H01=h01-sp0*sq1*invc, H02=h02-sp0*sq2*invc;
        float H10=h10-sp1*sq0*invc, H11=h11-sp1*sq1*invc, H12=h12-sp1*sq2*invc;
        float H20=h20-sp2*sq0*invc, H21=h21-sp2*sq1*invc, H22=h22-sp2*sq2*invc;

        float A[4][4];
        A[0][0] = H00 + H11 + H22;
        A[0][1] = H12 - H21;
        A[0][2] = H20 - H02;
        A[0][3] = H01 - H10;
        A[1][1] = H00 - H11 - H22;
        A[1][2] = H01 + H10;
        A[1][3] = H20 + H02;
        A[2][2] = -H00 + H11 - H22;
        A[2][3] = H12 + H21;
        A[3][3] = -H00 - H11 + H22;
        A[1][0]=A[0][1]; A[2][0]=A[0][2]; A[3][0]=A[0][3];
        A[2][1]=A[1][2]; A[3][1]=A[1][3]; A[3][2]=A[2][3];

        float V[4][4] = {{1,0,0,0},{0,1,0,0},{0,0,1,0},{0,0,0,1}};

        #pragma unroll
        for (int sweep = 0; sweep < 4; sweep++) {
            #pragma unroll
            for (int p = 0; p < 3; p++) {
                #pragma unroll
                for (int q = p + 1; q < 4; q++) {
                    float apq = A[p][q];
                    float theta = (A[q][q] - A[p][p]) * __fdividef(0.5f, apq);
                    float tt = __fdividef(1.0f, fabsf(theta) + __fsqrt_rn(fmaf(theta, theta, 1.0f)));
                    tt = (theta < 0.0f) ? -tt : tt;
                    bool ok = fabsf(apq) > 1e-30f;
                    float cc = ok ? rsqrtf(fmaf(tt, tt, 1.0f)) : 1.0f;
                    float ss = ok ? tt * cc : 0.0f;
                    #pragma unroll
                    for (int k = 0; k < 4; k++) {
                        float t1 = A[p][k], t2 = A[q][k];
                        A[p][k] = cc*t1 - ss*t2;
                        A[q][k] = ss*t1 + cc*t2;
                    }
                    #pragma unroll
                    for (int k = 0; k < 4; k++) {
                        float t1 = A[k][p], t2 = A[k][q];
                        A[k][p] = cc*t1 - ss*t2;
                        A[k][q] = ss*t1 + cc*t2;
                    }
                    #pragma unroll
                    for (int k = 0; k < 4; k++) {
                        float t1 = V[k][p], t2 = V[k][q];
                        V[k][p] = cc*t1 - ss*t2;
                        V[k][q] = ss*t1 + cc*t2;
                    }
                }
            }
        }

        int kbest = 0;
        float best = A[0][0];
        #pragma unroll
        for (int k = 1; k < 4; k++)
            if (A[k][k] > best) { best = A[k][k]; kbest = k; }
        float qw=V[0][kbest], qx=V[1][kbest], qy=V[2][kbest], qz=V[3][kbest];
        float qn = rsqrtf(qw*qw + qx*qx + qy*qy + qz*qz);
        qw*=qn; qx*=qn; qy*=qn; qz*=qn;

        float R00 = qw*qw + qx*qx - qy*qy - qz*qz;
        float R01 = 2.0f*(qx*qy - qw*qz);
        float R02 = 2.0f*(qx*qz + qw*qy);
        float R10 = 2.0f*(qx*qy + qw*qz);
        float R11 = qw*qw - qx*qx + qy*qy - qz*qz;
        float R12 = 2.0f*(qy*qz - qw*qx);
        float R20 = 2.0f*(qx*qz - qw*qy);
        float R21 = 2.0f*(qy*qz + qw*qx);
        float R22 = qw*qw - qx*qx - qy*qy + qz*qz;

        float tx = cqx - (R00*cpx + R01*cpy + R02*cpz);
        float ty = cqy - (R10*cpx + R11*cpy + R12*cpz);
        float tz = cqz - (R20*cpx + R21*cpy + R22*cpz);

        float4* w = (float4*)&g_RT[d * 12];
        w[0] = make_float4(R00, R01, R02, R10);
        w[1] = make_float4(R11, R12, R20, R21);
        w[2] = make_float4(R22, tx, ty, tz);
        st_rel(&g_rtflag[d], 1);
    }

    // ---- apply role: node n = t ----
    int n = t;
    float qx = pos[3*n], qy = pos[3*n+1], qz = pos[3*n+2];
    float px, py, pz;
    if (n < N_TW) {
        float3 P = xform(g_Mv[MAX_ORDER - 1], n / KTW, qx, qy, qz);
        px = P.x; py = P.y; pz = P.z;
    } else { px = qx; py = qy; pz = qz; }

    int d = n / 100;
    while (ld_acq(&g_rtflag[d]) == 0) { }

    const float4* r = (const float4*)&g_RT[d * 12];
    float4 R0 = r[0], R1 = r[1], R2 = r[2];
    out[3*n+0] = R0.x*px + R0.y*py + R0.z*pz + R2.y;
    out[3*n+1] = R0.w*px + R1.x*py + R1.y*pz + R2.z;
    out[3*n+2] = R1.z*px + R1.w*py + R2.x*pz + R2.w;
}

// ---------------------------------------------------------------------------
extern "C" void kernel_launch(void* const* d_in, const int* in_sizes, int n_in,
                              void* d_out, int out_size) {
    const float* pos   = (const float*)d_in[0];
    const float* info  = (const float*)d_in[1];
    const int*   anno  = (const int*)d_in[2];
    const float* eps   = (const float*)d_in[6];
    const float* uni   = (const float*)d_in[7];
    const int*   fprio = (const int*)d_in[8];
    float* out = (float*)d_out;

    k_fused<<<FUS_BLKS, NTHR>>>(pos, anno, info, eps, uni, fprio);
    k_reduce<<<(N_DOMAIN * 32 + 255) / 256, 256>>>(pos);
    k_sapply<<<(N_NODE + 255) / 256, 256>>>(pos, out);
}